// round 5
// baseline (speedup 1.0000x reference)
#include <cuda_runtime.h>
#include <cuda_fp16.h>
#include <cstdint>

// Shapes: x[4,1024,4096] f32, qweight[512,11008] i32 (8x4b along K),
// qzeros[32,1376] i32 (8x4b along N), scales[32,11008] f32, out[4096,11008] f32.
#define MDIM 4096
#define KDIM 4096
#define NDIM 11008

#define BM 128
#define BN 256
#define BK 64
#define THREADS 256
#define NIT (KDIM / BK)          // 64
#define GRID_M (MDIM / BM)       // 32
#define GRID_N (NDIM / BN)       // 43

#define ROWB 128                                  // 128B rows, XOR swizzle
#define A_STAGE (BM * ROWB)                       // 16384
#define B_STAGE (BN * ROWB)                       // 32768
#define SM_A 0                                    // 3 stages A
#define SM_B (3 * A_STAGE)                        // 3 stages B
#define SMEM_TOTAL (3 * A_STAGE + 3 * B_STAGE)    // 147456

// fp16 staging of x
__device__ __align__(16) __half g_xh[(size_t)MDIM * KDIM];   // 33.5 MB

// ---------------- prepass: x fp32 -> fp16 row-major ----------------
__global__ void cvt_x_kernel(const float* __restrict__ x) {
    size_t idx = (size_t)blockIdx.x * blockDim.x + threadIdx.x;   // one uint4 (8 halfs)
    if (idx >= (size_t)MDIM * KDIM / 8) return;
    const float4* xp = reinterpret_cast<const float4*>(x) + idx * 2;
    float4 a = xp[0], b = xp[1];
    __half2 h0 = __floats2half2_rn(a.x, a.y);
    __half2 h1 = __floats2half2_rn(a.z, a.w);
    __half2 h2 = __floats2half2_rn(b.x, b.y);
    __half2 h3 = __floats2half2_rn(b.z, b.w);
    uint4 o;
    o.x = *reinterpret_cast<uint32_t*>(&h0);
    o.y = *reinterpret_cast<uint32_t*>(&h1);
    o.z = *reinterpret_cast<uint32_t*>(&h2);
    o.w = *reinterpret_cast<uint32_t*>(&h3);
    reinterpret_cast<uint4*>(g_xh)[idx] = o;
}

// ---------------- PTX helpers ----------------
__device__ __forceinline__ void ldsm4(uint32_t* r, uint32_t addr) {
    asm volatile("ldmatrix.sync.aligned.m8n8.x4.shared.b16 {%0,%1,%2,%3}, [%4];"
                 : "=r"(r[0]), "=r"(r[1]), "=r"(r[2]), "=r"(r[3]) : "r"(addr));
}
__device__ __forceinline__ void mma16816(float* c, const uint32_t* a, uint32_t b0, uint32_t b1) {
    asm volatile("mma.sync.aligned.m16n8k16.row.col.f32.f16.f16.f32 "
                 "{%0,%1,%2,%3}, {%4,%5,%6,%7}, {%8,%9}, {%0,%1,%2,%3};"
                 : "+f"(c[0]), "+f"(c[1]), "+f"(c[2]), "+f"(c[3])
                 : "r"(a[0]), "r"(a[1]), "r"(a[2]), "r"(a[3]), "r"(b0), "r"(b1));
}
__device__ __forceinline__ void cp_async16(uint32_t dst, const void* src) {
    asm volatile("cp.async.cg.shared.global [%0], [%1], 16;" :: "r"(dst), "l"(src));
}
#define CP_COMMIT() asm volatile("cp.async.commit_group;" ::: "memory")
#define CP_WAIT(N)  asm volatile("cp.async.wait_group %0;" :: "n"(N) : "memory")

// ---------------- main fused GEMM ----------------
__global__ void __launch_bounds__(THREADS, 1) gemm_kernel(
    const int* __restrict__ qweight, const int* __restrict__ qzeros,
    const float* __restrict__ scales, float* __restrict__ out)
{
    extern __shared__ __align__(16) char smem[];
    const uint32_t smem_base = (uint32_t)__cvta_generic_to_shared(smem);

    const int t = threadIdx.x;
    const int wid = t >> 5;
    const int lane = t & 31;

    const int mtile = blockIdx.x & 31;          // mtile fastest: wave shares B cols + A in L2
    const int ntile = blockIdx.x >> 5;
    const int m0 = mtile * BM;
    const int n0 = ntile * BN;
    const int n = n0 + t;                       // this thread's B column (dequant duty)

    const int warp_m = wid >> 2;
    const int warp_n = wid & 3;

    float acc[4][8][4];
    #pragma unroll
    for (int i = 0; i < 4; ++i)
        #pragma unroll
        for (int j = 0; j < 8; ++j)
            #pragma unroll
            for (int k = 0; k < 4; ++k) acc[i][j][k] = 0.f;

    const __half* gA = g_xh + (size_t)m0 * KDIM;

    auto load_stage_A = [&](int s, int kblk) {
        const int k0 = kblk * BK;
        uint32_t base = smem_base + SM_A + s * A_STAGE;
        #pragma unroll
        for (int j = 0; j < 4; ++j) {           // 1024 x 16B chunks
            int idx = j * 256 + t;
            int row = idx >> 3, c = idx & 7;
            cp_async16(base + row * ROWB + ((c * 16) ^ ((row & 7) << 4)),
                       gA + (size_t)row * KDIM + k0 + c * 8);
        }
    };

    auto ldq = [&](uint32_t* q, int c) {
        #pragma unroll
        for (int p = 0; p < 8; ++p)
            q[p] = (uint32_t)qweight[(size_t)(c * 8 + p) * NDIM + n];
    };

    // (mz, s) per quant group for this thread's column, prefetched one group ahead
    auto ldzs = [&](int g, uint32_t& mz, uint32_t& s2) {
        uint32_t zz = ((uint32_t)qzeros[g * (NDIM / 8) + (n >> 3)] >> ((n & 7) * 4)) & 0xFu;
        mz = 0x64006400u | zz | (zz << 16);
        uint32_t hs = (uint32_t)__half_as_ushort(__float2half_rn(scales[(size_t)g * NDIM + n]));
        s2 = hs | (hs << 16);
    };

    auto dequant_sts = [&](int buf, const uint32_t* q, uint32_t mz, uint32_t s2) {
        char* bbase = smem + SM_B + buf * B_STAGE + t * ROWB;
        const __half2 mzh = *reinterpret_cast<const __half2*>(&mz);
        const __half2 sh  = *reinterpret_cast<const __half2*>(&s2);
        const int swz = (t & 7) << 4;
        #pragma unroll
        for (int p = 0; p < 8; ++p) {
            uint32_t qq = q[p];
            uint32_t a0 = ((qq         & 0xFu) | ((qq << 12) & 0xF0000u)) | 0x64006400u;
            uint32_t a1 = (((qq >> 8)  & 0xFu) | ((qq << 4)  & 0xF0000u)) | 0x64006400u;
            uint32_t a2 = (((qq >> 16) & 0xFu) | ((qq >> 4)  & 0xF0000u)) | 0x64006400u;
            uint32_t a3 = (((qq >> 24) & 0xFu) | ((qq >> 12) & 0xF0000u)) | 0x64006400u;
            __half2 w0 = __hmul2(__hsub2(*reinterpret_cast<__half2*>(&a0), mzh), sh);
            __half2 w1 = __hmul2(__hsub2(*reinterpret_cast<__half2*>(&a1), mzh), sh);
            __half2 w2 = __hmul2(__hsub2(*reinterpret_cast<__half2*>(&a2), mzh), sh);
            __half2 w3 = __hmul2(__hsub2(*reinterpret_cast<__half2*>(&a3), mzh), sh);
            uint4 v;
            v.x = *reinterpret_cast<uint32_t*>(&w0);
            v.y = *reinterpret_cast<uint32_t*>(&w1);
            v.z = *reinterpret_cast<uint32_t*>(&w2);
            v.w = *reinterpret_cast<uint32_t*>(&w3);
            *reinterpret_cast<uint4*>(bbase + ((p * 16) ^ swz)) = v;
        }
    };

    // ---- prologue ----
    load_stage_A(0, 0); CP_COMMIT();
    load_stage_A(1, 1); CP_COMMIT();

    uint32_t mz_cur, s_cur, mz_nxt, s_nxt;
    ldzs(0, mz_cur, s_cur);
    ldzs(1, mz_nxt, s_nxt);

    uint32_t q[8];
    ldq(q, 0);
    dequant_sts(0, q, mz_cur, s_cur);   // chunk 0 -> buf 0 (group 0)
    ldq(q, 1);

    // per-thread ldmatrix address components
    const int rA = lane & 15;
    const int cA = (lane >> 4) * 16;
    const int swzA = (lane & 7) << 4;
    const int rB = ((lane >> 3) & 1) * 8 + (lane & 7);
    const int cB = (lane >> 4) * 16;
    const int swzB = (lane & 7) << 4;

    uint32_t afrag[2][4][4];
    uint32_t bfrag[4][4];

    #pragma unroll 1
    for (int c = 0; c < NIT; ++c) {
        if (c + 2 < NIT) load_stage_A((c + 2) % 3, c + 2);
        CP_COMMIT();

        // dequant chunk c+1 into buf (c+1)%3; it uses group (c+2)>>1... no: group of
        // chunk (c+1) is ((c+1)*BK)/128 = (c+1)>>1.
        if (c + 1 < NIT) {
            if (c & 1) {            // group boundary: chunk c+1 starts group ((c+1)>>1)
                mz_cur = mz_nxt; s_cur = s_nxt;
                int gn = ((c + 1) >> 1) + 1;
                if (gn < KDIM / 128) ldzs(gn, mz_nxt, s_nxt);
            }
            dequant_sts((c + 1) % 3, q, mz_cur, s_cur);
        }
        if (c + 2 < NIT) ldq(q, c + 2);

        CP_WAIT(2);
        __syncthreads();

        const uint32_t aBase = smem_base + SM_A + (c % 3) * A_STAGE;
        const uint32_t bBase = smem_base + SM_B + (c % 3) * B_STAGE;

        // preload A kh=0
        #pragma unroll
        for (int mi = 0; mi < 4; ++mi) {
            int row = warp_m * 64 + mi * 16 + rA;
            ldsm4(afrag[0][mi], aBase + row * ROWB + (cA ^ swzA));
        }

        #pragma unroll
        for (int kh = 0; kh < 4; ++kh) {
            const int cur = kh & 1, nxt = cur ^ 1;
            // B frags for this kh (single-buffered)
            #pragma unroll
            for (int np = 0; np < 4; ++np) {
                int row = warp_n * 64 + np * 16 + rB;
                ldsm4(bfrag[np], bBase + row * ROWB + ((kh * 32 + cB) ^ swzB));
            }
            // prefetch A for kh+1
            if (kh < 3) {
                #pragma unroll
                for (int mi = 0; mi < 4; ++mi) {
                    int row = warp_m * 64 + mi * 16 + rA;
                    ldsm4(afrag[nxt][mi], aBase + row * ROWB + (((kh + 1) * 32 + cA) ^ swzA));
                }
            }
            #pragma unroll
            for (int np = 0; np < 4; ++np)
                #pragma unroll
                for (int mi = 0; mi < 4; ++mi) {
                    mma16816(acc[mi][2 * np],     afrag[cur][mi], bfrag[np][0], bfrag[np][2]);
                    mma16816(acc[mi][2 * np + 1], afrag[cur][mi], bfrag[np][1], bfrag[np][3]);
                }
        }
    }
    CP_WAIT(0);

    // ---- epilogue: streaming float2 stores ----
    const int mBase = m0 + warp_m * 64;
    const int nBase = n0 + warp_n * 64;
    const int r0 = lane >> 2;
    const int cpair = (lane & 3) * 2;
    #pragma unroll
    for (int mi = 0; mi < 4; ++mi) {
        #pragma unroll
        for (int ni = 0; ni < 8; ++ni) {
            float* p0 = out + (size_t)(mBase + mi * 16 + r0) * NDIM + nBase + ni * 8 + cpair;
            float* p1 = out + (size_t)(mBase + mi * 16 + r0 + 8) * NDIM + nBase + ni * 8 + cpair;
            __stcs(reinterpret_cast<float2*>(p0), make_float2(acc[mi][ni][0], acc[mi][ni][1]));
            __stcs(reinterpret_cast<float2*>(p1), make_float2(acc[mi][ni][2], acc[mi][ni][3]));
        }
    }
}

extern "C" void kernel_launch(void* const* d_in, const int* in_sizes, int n_in,
                              void* d_out, int out_size) {
    const float* x  = (const float*)d_in[0];
    const int* qw   = (const int*)d_in[1];
    const int* qz   = (const int*)d_in[2];
    const float* sc = (const float*)d_in[3];
    float* out      = (float*)d_out;

    cudaFuncSetAttribute(gemm_kernel, cudaFuncAttributeMaxDynamicSharedMemorySize, SMEM_TOTAL);

    cvt_x_kernel<<<(MDIM * KDIM / 8 + 255) / 256, 256>>>(x);
    gemm_kernel<<<GRID_M * GRID_N, THREADS, SMEM_TOTAL>>>(qw, qz, sc, out);
}

// round 6
// speedup vs baseline: 1.3195x; 1.3195x over previous
#include <cuda_runtime.h>
#include <cuda_fp16.h>
#include <cstdint>

// Shapes: x[4,1024,4096] f32, qweight[512,11008] i32 (8x4b along K),
// qzeros[32,1376] i32 (8x4b along N), scales[32,11008] f32, out[4096,11008] f32.
#define MDIM 4096
#define KDIM 4096
#define NDIM 11008

#define BM 128
#define BN 128
#define BK 64
#define STAGES 3
#define THREADS 256
#define NIT (KDIM / BK)          // 64
#define GRID_M (MDIM / BM)       // 32
#define GRID_N (NDIM / BN)       // 86

#define ROWB 128                                  // 128B rows, XOR swizzle
#define A_STAGE (BM * ROWB)                       // 16384
#define B_STAGE (BN * ROWB)                       // 16384
#define STAGE_BYTES (A_STAGE + B_STAGE)           // 32768
#define SMEM_TOTAL (STAGE_BYTES * STAGES)         // 98304  -> 2 CTAs/SM

// fp16 staging of A (x) and dequantized W^T (N-major, K contiguous)
__device__ __align__(16) __half g_xh[(size_t)MDIM * KDIM];   // 33.5 MB
__device__ __align__(16) __half g_wt[(size_t)NDIM * KDIM];   // 90.2 MB

// ---------------- prepass 1: x fp32 -> fp16 row-major ----------------
__global__ void cvt_x_kernel(const float* __restrict__ x) {
    size_t idx = (size_t)blockIdx.x * blockDim.x + threadIdx.x;   // one uint4 (8 halfs)
    if (idx >= (size_t)MDIM * KDIM / 8) return;
    const float4* xp = reinterpret_cast<const float4*>(x) + idx * 2;
    float4 a = xp[0], b = xp[1];
    __half2 h0 = __floats2half2_rn(a.x, a.y);
    __half2 h1 = __floats2half2_rn(a.z, a.w);
    __half2 h2 = __floats2half2_rn(b.x, b.y);
    __half2 h3 = __floats2half2_rn(b.z, b.w);
    uint4 o;
    o.x = *reinterpret_cast<uint32_t*>(&h0);
    o.y = *reinterpret_cast<uint32_t*>(&h1);
    o.z = *reinterpret_cast<uint32_t*>(&h2);
    o.w = *reinterpret_cast<uint32_t*>(&h3);
    reinterpret_cast<uint4*>(g_xh)[idx] = o;
}

// ---------------- prepass 2: dequant + transpose via smem tile ----------------
__global__ void __launch_bounds__(256) dequant_kernel(const int* __restrict__ qweight,
                                                      const int* __restrict__ qzeros,
                                                      const float* __restrict__ scales) {
    __shared__ __align__(16) uint8_t tile[64 * 128];
    const int t = threadIdx.x;
    const int n0 = blockIdx.x * 64;
    const int k0 = blockIdx.y * 64;          // in halfs
    const int kp0 = blockIdx.y * 8;          // packed-int32 row base
    const int g = k0 >> 7;                   // quant group (GROUP=128)

    const int nl = t & 63;
    const int n = n0 + nl;
    const int z = ((uint32_t)qzeros[g * (NDIM / 8) + (n >> 3)] >> ((n & 7) * 4)) & 0xF;
    const float s = scales[(size_t)g * NDIM + n];

    #pragma unroll
    for (int i = 0; i < 2; ++i) {
        int item = i * 256 + t;
        int kp = item >> 6;                  // 0..7
        uint32_t q = (uint32_t)qweight[(size_t)(kp0 + kp) * NDIM + n];
        __half h[8];
        #pragma unroll
        for (int j = 0; j < 8; ++j) {
            int v = (q >> (4 * j)) & 0xF;
            h[j] = __float2half_rn((float)(v - z) * s);
        }
        int colb = (kp * 16) ^ ((nl & 7) << 4);
        *reinterpret_cast<uint4*>(tile + nl * 128 + colb) = *reinterpret_cast<uint4*>(h);
    }
    __syncthreads();
    #pragma unroll
    for (int i = 0; i < 8; ++i) {
        int idx = i * 256 + t;
        int row = idx >> 5, col = idx & 31;  // col in uint32 units
        uint32_t v = *reinterpret_cast<uint32_t*>(tile + row * 128 + ((col * 4) ^ ((row & 7) << 4)));
        *reinterpret_cast<uint32_t*>(&g_wt[(size_t)(n0 + row) * KDIM + k0 + col * 2]) = v;
    }
}

// ---------------- PTX helpers ----------------
__device__ __forceinline__ void ldsm4(uint32_t* r, uint32_t addr) {
    asm volatile("ldmatrix.sync.aligned.m8n8.x4.shared.b16 {%0,%1,%2,%3}, [%4];"
                 : "=r"(r[0]), "=r"(r[1]), "=r"(r[2]), "=r"(r[3]) : "r"(addr));
}
__device__ __forceinline__ void mma16816(float* c, const uint32_t* a, uint32_t b0, uint32_t b1) {
    asm volatile("mma.sync.aligned.m16n8k16.row.col.f32.f16.f16.f32 "
                 "{%0,%1,%2,%3}, {%4,%5,%6,%7}, {%8,%9}, {%0,%1,%2,%3};"
                 : "+f"(c[0]), "+f"(c[1]), "+f"(c[2]), "+f"(c[3])
                 : "r"(a[0]), "r"(a[1]), "r"(a[2]), "r"(a[3]), "r"(b0), "r"(b1));
}
__device__ __forceinline__ void cp_async16(uint32_t dst, const void* src) {
    asm volatile("cp.async.cg.shared.global [%0], [%1], 16;" :: "r"(dst), "l"(src));
}
#define CP_COMMIT() asm volatile("cp.async.commit_group;" ::: "memory")
#define CP_WAIT(N)  asm volatile("cp.async.wait_group %0;" :: "n"(N) : "memory")

// ---------------- main GEMM: 128x128 tile, 2 CTAs/SM ----------------
__global__ void __launch_bounds__(THREADS, 2) gemm_kernel(float* __restrict__ out) {
    extern __shared__ __align__(16) char smem[];
    const uint32_t smem_base = (uint32_t)__cvta_generic_to_shared(smem);

    const int t = threadIdx.x;
    const int wid = t >> 5;
    const int lane = t & 31;

    const int mtile = blockIdx.x & 31;          // mtile fastest: wave shares A fully + B slices in L2
    const int ntile = blockIdx.x >> 5;
    const int m0 = mtile * BM;
    const int n0 = ntile * BN;

    const int warp_m = wid & 3;                 // 4 slabs x 32 rows
    const int warp_n = wid >> 2;                // 2 slabs x 64 cols

    float acc[2][8][4];
    #pragma unroll
    for (int i = 0; i < 2; ++i)
        #pragma unroll
        for (int j = 0; j < 8; ++j)
            #pragma unroll
            for (int k = 0; k < 4; ++k) acc[i][j][k] = 0.f;

    const __half* gA = g_xh + (size_t)m0 * KDIM;
    const __half* gB = g_wt + (size_t)n0 * KDIM;

    auto load_stage = [&](int s, int kblk) {
        const int k0 = kblk * BK;
        uint32_t base = smem_base + s * STAGE_BYTES;
        #pragma unroll
        for (int j = 0; j < 4; ++j) {           // A: 1024 x 16B chunks
            int idx = j * 256 + t;
            int row = idx >> 3, c = idx & 7;
            cp_async16(base + row * ROWB + ((c * 16) ^ ((row & 7) << 4)),
                       gA + (size_t)row * KDIM + k0 + c * 8);
        }
        #pragma unroll
        for (int j = 0; j < 4; ++j) {           // B: 1024 x 16B chunks
            int idx = j * 256 + t;
            int row = idx >> 3, c = idx & 7;
            cp_async16(base + A_STAGE + row * ROWB + ((c * 16) ^ ((row & 7) << 4)),
                       gB + (size_t)row * KDIM + k0 + c * 8);
        }
        CP_COMMIT();
    };

    #pragma unroll
    for (int s = 0; s < STAGES - 1; ++s) load_stage(s, s);

    const int rA = lane & 15;
    const int cA = (lane >> 4) * 16;
    const int swzA = (lane & 7) << 4;
    const int rB = ((lane >> 3) & 1) * 8 + (lane & 7);
    const int cB = (lane >> 4) * 16;
    const int swzB = (lane & 7) << 4;

    uint32_t afrag[2][2][4];     // double-buffered across kh
    uint32_t bfrag[4][4];        // single-buffered (reg budget)

    #pragma unroll 1
    for (int it = 0; it < NIT; ++it) {
        CP_WAIT(STAGES - 2);
        __syncthreads();

        if (it + STAGES - 1 < NIT) load_stage((it + STAGES - 1) % STAGES, it + STAGES - 1);

        const int s = it % STAGES;
        const uint32_t aBase = smem_base + s * STAGE_BYTES;
        const uint32_t bBase = aBase + A_STAGE;

        // preload A kh=0
        #pragma unroll
        for (int mi = 0; mi < 2; ++mi) {
            int row = warp_m * 32 + mi * 16 + rA;
            ldsm4(afrag[0][mi], aBase + row * ROWB + (cA ^ swzA));
        }

        #pragma unroll
        for (int kh = 0; kh < 4; ++kh) {        // four k16 steps of BK=64
            const int cur = kh & 1, nxt = cur ^ 1;
            // B frags for this kh
            #pragma unroll
            for (int np = 0; np < 4; ++np) {
                int row = warp_n * 64 + np * 16 + rB;
                ldsm4(bfrag[np], bBase + row * ROWB + ((kh * 32 + cB) ^ swzB));
            }
            // prefetch A for kh+1
            if (kh < 3) {
                #pragma unroll
                for (int mi = 0; mi < 2; ++mi) {
                    int row = warp_m * 32 + mi * 16 + rA;
                    ldsm4(afrag[nxt][mi], aBase + row * ROWB + (((kh + 1) * 32 + cA) ^ swzA));
                }
            }
            #pragma unroll
            for (int np = 0; np < 4; ++np)
                #pragma unroll
                for (int mi = 0; mi < 2; ++mi) {
                    mma16816(acc[mi][2 * np],     afrag[cur][mi], bfrag[np][0], bfrag[np][2]);
                    mma16816(acc[mi][2 * np + 1], afrag[cur][mi], bfrag[np][1], bfrag[np][3]);
                }
        }
    }
    CP_WAIT(0);

    // ---- epilogue: streaming float2 stores ----
    const int mBase = m0 + warp_m * 32;
    const int nBase = n0 + warp_n * 64;
    const int r0 = lane >> 2;
    const int cpair = (lane & 3) * 2;
    #pragma unroll
    for (int mi = 0; mi < 2; ++mi) {
        #pragma unroll
        for (int ni = 0; ni < 8; ++ni) {
            float* p0 = out + (size_t)(mBase + mi * 16 + r0) * NDIM + nBase + ni * 8 + cpair;
            float* p1 = out + (size_t)(mBase + mi * 16 + r0 + 8) * NDIM + nBase + ni * 8 + cpair;
            __stcs(reinterpret_cast<float2*>(p0), make_float2(acc[mi][ni][0], acc[mi][ni][1]));
            __stcs(reinterpret_cast<float2*>(p1), make_float2(acc[mi][ni][2], acc[mi][ni][3]));
        }
    }
}

extern "C" void kernel_launch(void* const* d_in, const int* in_sizes, int n_in,
                              void* d_out, int out_size) {
    const float* x  = (const float*)d_in[0];
    const int* qw   = (const int*)d_in[1];
    const int* qz   = (const int*)d_in[2];
    const float* sc = (const float*)d_in[3];
    float* out      = (float*)d_out;

    cudaFuncSetAttribute(gemm_kernel, cudaFuncAttributeMaxDynamicSharedMemorySize, SMEM_TOTAL);

    cvt_x_kernel<<<(MDIM * KDIM / 8 + 255) / 256, 256>>>(x);
    dim3 dq_grid(NDIM / 64, KDIM / 64);
    dequant_kernel<<<dq_grid, 256>>>(qw, qz, sc);
    gemm_kernel<<<GRID_M * GRID_N, THREADS, SMEM_TOTAL>>>(out);
}

// round 7
// speedup vs baseline: 1.3227x; 1.0024x over previous
#include <cuda_runtime.h>
#include <cuda_fp16.h>
#include <cstdint>

// Shapes: x[4,1024,4096] f32, qweight[512,11008] i32 (8x4b along K),
// qzeros[32,1376] i32 (8x4b along N), scales[32,11008] f32, out[4096,11008] f32.
#define MDIM 4096
#define KDIM 4096
#define NDIM 11008

#define BM 128
#define BN 128
#define BK 64
#define STAGES 3
#define THREADS 256
#define NIT (KDIM / BK)          // 64
#define GRID_M (MDIM / BM)       // 32
#define GRID_N (NDIM / BN)       // 86

#define ROWB 128                                  // 128B rows, XOR swizzle
#define A_STAGE (BM * ROWB)                       // 16384
#define B_STAGE (BN * ROWB)                       // 16384
#define STAGE_BYTES (A_STAGE + B_STAGE)           // 32768
#define SMEM_TOTAL (STAGE_BYTES * STAGES)         // 98304  -> 2 CTAs/SM

#define CVT_BLOCKS (MDIM * KDIM / 8 / 256)        // 8192
#define DQ_BX (NDIM / 64)                         // 172
#define DQ_BY (KDIM / 64)                         // 64
#define PREP_BLOCKS (CVT_BLOCKS + DQ_BX * DQ_BY)  // 19200

// fp16 staging of A (x) and dequantized W^T (N-major, K contiguous)
__device__ __align__(16) __half g_xh[(size_t)MDIM * KDIM];   // 33.5 MB
__device__ __align__(16) __half g_wt[(size_t)NDIM * KDIM];   // 90.2 MB

// ---------------- merged prepass: x->fp16  +  dequant/transpose ----------------
__global__ void __launch_bounds__(256) prep_kernel(const float* __restrict__ x,
                                                   const int* __restrict__ qweight,
                                                   const int* __restrict__ qzeros,
                                                   const float* __restrict__ scales) {
    const int t = threadIdx.x;
    if (blockIdx.x < CVT_BLOCKS) {
        // ---- x fp32 -> fp16 row-major, one uint4 (8 halfs) per thread ----
        size_t idx = (size_t)blockIdx.x * 256 + t;
        const float4* xp = reinterpret_cast<const float4*>(x) + idx * 2;
        float4 a = xp[0], b = xp[1];
        __half2 h0 = __floats2half2_rn(a.x, a.y);
        __half2 h1 = __floats2half2_rn(a.z, a.w);
        __half2 h2 = __floats2half2_rn(b.x, b.y);
        __half2 h3 = __floats2half2_rn(b.z, b.w);
        uint4 o;
        o.x = *reinterpret_cast<uint32_t*>(&h0);
        o.y = *reinterpret_cast<uint32_t*>(&h1);
        o.z = *reinterpret_cast<uint32_t*>(&h2);
        o.w = *reinterpret_cast<uint32_t*>(&h3);
        reinterpret_cast<uint4*>(g_xh)[idx] = o;
        return;
    }
    // ---- dequant + transpose via smem tile: 64 n x 64 k ----
    __shared__ __align__(16) uint8_t tile[64 * 128];
    const int b = blockIdx.x - CVT_BLOCKS;
    const int n0 = (b % DQ_BX) * 64;
    const int by = b / DQ_BX;
    const int k0 = by * 64;                  // in halfs
    const int kp0 = by * 8;                  // packed-int32 row base
    const int g = k0 >> 7;                   // quant group (GROUP=128)

    const int nl = t & 63;
    const int n = n0 + nl;
    const int z = ((uint32_t)qzeros[g * (NDIM / 8) + (n >> 3)] >> ((n & 7) * 4)) & 0xF;
    const float s = scales[(size_t)g * NDIM + n];

    #pragma unroll
    for (int i = 0; i < 2; ++i) {
        int item = i * 256 + t;
        int kp = item >> 6;                  // 0..7
        uint32_t q = (uint32_t)qweight[(size_t)(kp0 + kp) * NDIM + n];
        __half h[8];
        #pragma unroll
        for (int j = 0; j < 8; ++j) {
            int v = (q >> (4 * j)) & 0xF;
            h[j] = __float2half_rn((float)(v - z) * s);
        }
        int colb = (kp * 16) ^ ((nl & 7) << 4);
        *reinterpret_cast<uint4*>(tile + nl * 128 + colb) = *reinterpret_cast<uint4*>(h);
    }
    __syncthreads();
    #pragma unroll
    for (int i = 0; i < 8; ++i) {
        int idx = i * 256 + t;
        int row = idx >> 5, col = idx & 31;  // col in uint32 units
        uint32_t v = *reinterpret_cast<uint32_t*>(tile + row * 128 + ((col * 4) ^ ((row & 7) << 4)));
        __stcs(reinterpret_cast<uint32_t*>(&g_wt[(size_t)(n0 + row) * KDIM + k0 + col * 2]), v);
    }
}

// ---------------- PTX helpers ----------------
__device__ __forceinline__ void ldsm4(uint32_t* r, uint32_t addr) {
    asm volatile("ldmatrix.sync.aligned.m8n8.x4.shared.b16 {%0,%1,%2,%3}, [%4];"
                 : "=r"(r[0]), "=r"(r[1]), "=r"(r[2]), "=r"(r[3]) : "r"(addr));
}
__device__ __forceinline__ void mma16816(float* c, const uint32_t* a, uint32_t b0, uint32_t b1) {
    asm volatile("mma.sync.aligned.m16n8k16.row.col.f32.f16.f16.f32 "
                 "{%0,%1,%2,%3}, {%4,%5,%6,%7}, {%8,%9}, {%0,%1,%2,%3};"
                 : "+f"(c[0]), "+f"(c[1]), "+f"(c[2]), "+f"(c[3])
                 : "r"(a[0]), "r"(a[1]), "r"(a[2]), "r"(a[3]), "r"(b0), "r"(b1));
}
__device__ __forceinline__ void cp_async16(uint32_t dst, const void* src) {
    asm volatile("cp.async.cg.shared.global [%0], [%1], 16;" :: "r"(dst), "l"(src));
}
#define CP_COMMIT() asm volatile("cp.async.commit_group;" ::: "memory")
#define CP_WAIT(N)  asm volatile("cp.async.wait_group %0;" :: "n"(N) : "memory")

// ---------------- main GEMM: 128x128 tile, 2 CTAs/SM ----------------
__global__ void __launch_bounds__(THREADS, 2) gemm_kernel(float* __restrict__ out) {
    extern __shared__ __align__(16) char smem[];
    const uint32_t smem_base = (uint32_t)__cvta_generic_to_shared(smem);

    const int t = threadIdx.x;
    const int wid = t >> 5;
    const int lane = t & 31;

    const int mtile = blockIdx.x & 31;          // mtile fastest: wave shares A fully + B slices in L2
    const int ntile = blockIdx.x >> 5;
    const int m0 = mtile * BM;
    const int n0 = ntile * BN;

    const int warp_m = wid & 3;                 // 4 slabs x 32 rows
    const int warp_n = wid >> 2;                // 2 slabs x 64 cols

    float acc[2][8][4];
    #pragma unroll
    for (int i = 0; i < 2; ++i)
        #pragma unroll
        for (int j = 0; j < 8; ++j)
            #pragma unroll
            for (int k = 0; k < 4; ++k) acc[i][j][k] = 0.f;

    const __half* gA = g_xh + (size_t)m0 * KDIM;
    const __half* gB = g_wt + (size_t)n0 * KDIM;

    auto load_stage = [&](int s, int kblk) {
        const int k0 = kblk * BK;
        uint32_t base = smem_base + s * STAGE_BYTES;
        #pragma unroll
        for (int j = 0; j < 4; ++j) {           // A: 1024 x 16B chunks
            int idx = j * 256 + t;
            int row = idx >> 3, c = idx & 7;
            cp_async16(base + row * ROWB + ((c * 16) ^ ((row & 7) << 4)),
                       gA + (size_t)row * KDIM + k0 + c * 8);
        }
        #pragma unroll
        for (int j = 0; j < 4; ++j) {           // B: 1024 x 16B chunks
            int idx = j * 256 + t;
            int row = idx >> 3, c = idx & 7;
            cp_async16(base + A_STAGE + row * ROWB + ((c * 16) ^ ((row & 7) << 4)),
                       gB + (size_t)row * KDIM + k0 + c * 8);
        }
        CP_COMMIT();
    };

    #pragma unroll
    for (int s = 0; s < STAGES - 1; ++s) load_stage(s, s);

    const int rA = lane & 15;
    const int cA = (lane >> 4) * 16;
    const int swzA = (lane & 7) << 4;
    const int rB = ((lane >> 3) & 1) * 8 + (lane & 7);
    const int cB = (lane >> 4) * 16;
    const int swzB = (lane & 7) << 4;

    uint32_t afrag[2][2][4];     // double-buffered across kh
    uint32_t bfrag[4][4];        // single-buffered (reg budget)

    #pragma unroll 1
    for (int it = 0; it < NIT; ++it) {
        CP_WAIT(STAGES - 2);
        __syncthreads();

        if (it + STAGES - 1 < NIT) load_stage((it + STAGES - 1) % STAGES, it + STAGES - 1);

        const int s = it % STAGES;
        const uint32_t aBase = smem_base + s * STAGE_BYTES;
        const uint32_t bBase = aBase + A_STAGE;

        // preload A kh=0
        #pragma unroll
        for (int mi = 0; mi < 2; ++mi) {
            int row = warp_m * 32 + mi * 16 + rA;
            ldsm4(afrag[0][mi], aBase + row * ROWB + (cA ^ swzA));
        }

        #pragma unroll
        for (int kh = 0; kh < 4; ++kh) {        // four k16 steps of BK=64
            const int cur = kh & 1, nxt = cur ^ 1;
            // B frags for this kh
            #pragma unroll
            for (int np = 0; np < 4; ++np) {
                int row = warp_n * 64 + np * 16 + rB;
                ldsm4(bfrag[np], bBase + row * ROWB + ((kh * 32 + cB) ^ swzB));
            }
            // prefetch A for kh+1
            if (kh < 3) {
                #pragma unroll
                for (int mi = 0; mi < 2; ++mi) {
                    int row = warp_m * 32 + mi * 16 + rA;
                    ldsm4(afrag[nxt][mi], aBase + row * ROWB + (((kh + 1) * 32 + cA) ^ swzA));
                }
            }
            #pragma unroll
            for (int np = 0; np < 4; ++np)
                #pragma unroll
                for (int mi = 0; mi < 2; ++mi) {
                    mma16816(acc[mi][2 * np],     afrag[cur][mi], bfrag[np][0], bfrag[np][2]);
                    mma16816(acc[mi][2 * np + 1], afrag[cur][mi], bfrag[np][1], bfrag[np][3]);
                }
        }
    }
    CP_WAIT(0);

    // ---- epilogue: streaming float2 stores ----
    const int mBase = m0 + warp_m * 32;
    const int nBase = n0 + warp_n * 64;
    const int r0 = lane >> 2;
    const int cpair = (lane & 3) * 2;
    #pragma unroll
    for (int mi = 0; mi < 2; ++mi) {
        #pragma unroll
        for (int ni = 0; ni < 8; ++ni) {
            float* p0 = out + (size_t)(mBase + mi * 16 + r0) * NDIM + nBase + ni * 8 + cpair;
            float* p1 = out + (size_t)(mBase + mi * 16 + r0 + 8) * NDIM + nBase + ni * 8 + cpair;
            __stcs(reinterpret_cast<float2*>(p0), make_float2(acc[mi][ni][0], acc[mi][ni][1]));
            __stcs(reinterpret_cast<float2*>(p1), make_float2(acc[mi][ni][2], acc[mi][ni][3]));
        }
    }
}

extern "C" void kernel_launch(void* const* d_in, const int* in_sizes, int n_in,
                              void* d_out, int out_size) {
    const float* x  = (const float*)d_in[0];
    const int* qw   = (const int*)d_in[1];
    const int* qz   = (const int*)d_in[2];
    const float* sc = (const float*)d_in[3];
    float* out      = (float*)d_out;

    cudaFuncSetAttribute(gemm_kernel, cudaFuncAttributeMaxDynamicSharedMemorySize, SMEM_TOTAL);

    prep_kernel<<<PREP_BLOCKS, 256>>>(x, qw, qz, sc);
    gemm_kernel<<<GRID_M * GRID_N, THREADS, SMEM_TOTAL>>>(out);
}

// round 8
// speedup vs baseline: 1.4189x; 1.0727x over previous
#include <cuda_runtime.h>
#include <cuda_fp16.h>
#include <cstdint>

// Shapes: x[4,1024,4096] f32, qweight[512,11008] i32 (8x4b along K),
// qzeros[32,1376] i32 (8x4b along N), scales[32,11008] f32, out[4096,11008] f32.
#define MDIM 4096
#define KDIM 4096
#define NDIM 11008

#define BM 128
#define BN 128
#define BK 64
#define STAGES 3
#define THREADS 256
#define NIT (KDIM / BK)          // 64
#define GRID_M (MDIM / BM)       // 32
#define GRID_N (NDIM / BN)       // 86

#define ROWB 128                                  // 128B rows, XOR swizzle
#define A_STAGE (BM * ROWB)                       // 16384
#define B_STAGE (BN * ROWB)                       // 16384
#define STAGE_BYTES (A_STAGE + B_STAGE)           // 32768
#define SMEM_TOTAL (STAGE_BYTES * STAGES)         // 98304  -> 2 CTAs/SM

#define CVT_BLOCKS (MDIM * KDIM / 8 / 256)        // 8192
#define DQ_BX (NDIM / 64)                         // 172
#define DQ_BY (KDIM / 64)                         // 64
#define PREP_BLOCKS (CVT_BLOCKS + DQ_BX * DQ_BY)  // 19200

// fp16 staging of A (x) and dequantized W^T (N-major, K contiguous)
__device__ __align__(16) __half g_xh[(size_t)MDIM * KDIM];   // 33.5 MB
__device__ __align__(16) __half g_wt[(size_t)NDIM * KDIM];   // 90.2 MB

// ---------------- merged prepass: x->fp16  +  dequant/transpose ----------------
__global__ void __launch_bounds__(256) prep_kernel(const float* __restrict__ x,
                                                   const int* __restrict__ qweight,
                                                   const int* __restrict__ qzeros,
                                                   const float* __restrict__ scales) {
    const int t = threadIdx.x;
    if (blockIdx.x < CVT_BLOCKS) {
        size_t idx = (size_t)blockIdx.x * 256 + t;
        const float4* xp = reinterpret_cast<const float4*>(x) + idx * 2;
        float4 a = xp[0], b = xp[1];
        __half2 h0 = __floats2half2_rn(a.x, a.y);
        __half2 h1 = __floats2half2_rn(a.z, a.w);
        __half2 h2 = __floats2half2_rn(b.x, b.y);
        __half2 h3 = __floats2half2_rn(b.z, b.w);
        uint4 o;
        o.x = *reinterpret_cast<uint32_t*>(&h0);
        o.y = *reinterpret_cast<uint32_t*>(&h1);
        o.z = *reinterpret_cast<uint32_t*>(&h2);
        o.w = *reinterpret_cast<uint32_t*>(&h3);
        reinterpret_cast<uint4*>(g_xh)[idx] = o;
        return;
    }
    __shared__ __align__(16) uint8_t tile[64 * 128];
    const int b = blockIdx.x - CVT_BLOCKS;
    const int n0 = (b % DQ_BX) * 64;
    const int by = b / DQ_BX;
    const int k0 = by * 64;
    const int kp0 = by * 8;
    const int g = k0 >> 7;

    const int nl = t & 63;
    const int n = n0 + nl;
    const int z = ((uint32_t)qzeros[g * (NDIM / 8) + (n >> 3)] >> ((n & 7) * 4)) & 0xF;
    const float s = scales[(size_t)g * NDIM + n];

    #pragma unroll
    for (int i = 0; i < 2; ++i) {
        int item = i * 256 + t;
        int kp = item >> 6;
        uint32_t q = (uint32_t)qweight[(size_t)(kp0 + kp) * NDIM + n];
        __half h[8];
        #pragma unroll
        for (int j = 0; j < 8; ++j) {
            int v = (q >> (4 * j)) & 0xF;
            h[j] = __float2half_rn((float)(v - z) * s);
        }
        int colb = (kp * 16) ^ ((nl & 7) << 4);
        *reinterpret_cast<uint4*>(tile + nl * 128 + colb) = *reinterpret_cast<uint4*>(h);
    }
    __syncthreads();
    #pragma unroll
    for (int i = 0; i < 8; ++i) {
        int idx = i * 256 + t;
        int row = idx >> 5, col = idx & 31;
        uint32_t v = *reinterpret_cast<uint32_t*>(tile + row * 128 + ((col * 4) ^ ((row & 7) << 4)));
        __stcs(reinterpret_cast<uint32_t*>(&g_wt[(size_t)(n0 + row) * KDIM + k0 + col * 2]), v);
    }
}

// ---------------- PTX helpers ----------------
__device__ __forceinline__ void ldsm4(uint32_t* r, uint32_t addr) {
    asm volatile("ldmatrix.sync.aligned.m8n8.x4.shared.b16 {%0,%1,%2,%3}, [%4];"
                 : "=r"(r[0]), "=r"(r[1]), "=r"(r[2]), "=r"(r[3]) : "r"(addr));
}
__device__ __forceinline__ void mma16816(float* c, const uint32_t* a, uint32_t b0, uint32_t b1) {
    asm volatile("mma.sync.aligned.m16n8k16.row.col.f32.f16.f16.f32 "
                 "{%0,%1,%2,%3}, {%4,%5,%6,%7}, {%8,%9}, {%0,%1,%2,%3};"
                 : "+f"(c[0]), "+f"(c[1]), "+f"(c[2]), "+f"(c[3])
                 : "r"(a[0]), "r"(a[1]), "r"(a[2]), "r"(a[3]), "r"(b0), "r"(b1));
}
__device__ __forceinline__ void cp_async16(uint32_t dst, const void* src) {
    asm volatile("cp.async.cg.shared.global [%0], [%1], 16;" :: "r"(dst), "l"(src));
}
#define CP_COMMIT() asm volatile("cp.async.commit_group;" ::: "memory")
#define CP_WAIT(N)  asm volatile("cp.async.wait_group %0;" :: "n"(N) : "memory")

// ---------------- main GEMM: 128x128 tile, 2 CTAs/SM, loads interleaved ----------------
__global__ void __launch_bounds__(THREADS, 2) gemm_kernel(float* __restrict__ out) {
    extern __shared__ __align__(16) char smem[];
    const uint32_t smem_base = (uint32_t)__cvta_generic_to_shared(smem);

    const int t = threadIdx.x;
    const int wid = t >> 5;
    const int lane = t & 31;

    const int mtile = blockIdx.x & 31;          // mtile fastest: wave shares A fully + B slices in L2
    const int ntile = blockIdx.x >> 5;
    const int m0 = mtile * BM;
    const int n0 = ntile * BN;

    const int warp_m = wid & 3;                 // 4 slabs x 32 rows
    const int warp_n = wid >> 2;                // 2 slabs x 64 cols

    float acc[2][8][4];
    #pragma unroll
    for (int i = 0; i < 2; ++i)
        #pragma unroll
        for (int j = 0; j < 8; ++j)
            #pragma unroll
            for (int k = 0; k < 4; ++k) acc[i][j][k] = 0.f;

    const __half* gA = g_xh + (size_t)m0 * KDIM;
    const __half* gB = g_wt + (size_t)n0 * KDIM;

    // per-thread cp.async source/dest components
    const int ldRow = t >> 3;                   // 0..31 (row block step 32)
    const int ldCol = t & 7;                    // 16B chunk
    const int ldSwz = ((ldRow & 7) << 4);
    const uint32_t ldDstOff = ldRow * ROWB + ((ldCol * 16) ^ ldSwz);

    auto issue_A = [&](int s, int kblk) {
        const int k0 = kblk * BK;
        uint32_t base = smem_base + s * STAGE_BYTES + ldDstOff;
        const __half* src = gA + (size_t)ldRow * KDIM + k0 + ldCol * 8;
        #pragma unroll
        for (int j = 0; j < 4; ++j)
            cp_async16(base + j * 32 * ROWB, src + (size_t)(j * 32) * KDIM);
    };
    auto issue_B = [&](int s, int kblk) {
        const int k0 = kblk * BK;
        uint32_t base = smem_base + s * STAGE_BYTES + A_STAGE + ldDstOff;
        const __half* src = gB + (size_t)ldRow * KDIM + k0 + ldCol * 8;
        #pragma unroll
        for (int j = 0; j < 4; ++j)
            cp_async16(base + j * 32 * ROWB, src + (size_t)(j * 32) * KDIM);
    };

    // prologue: stages 0 and 1 in flight
    issue_A(0, 0); issue_B(0, 0); CP_COMMIT();
    issue_A(1, 1); issue_B(1, 1); CP_COMMIT();
    CP_WAIT(1);
    __syncthreads();

    const int rA = lane & 15;
    const int cA = (lane >> 4) * 16;
    const int swzA = (lane & 7) << 4;
    const int rB = ((lane >> 3) & 1) * 8 + (lane & 7);
    const int cB = (lane >> 4) * 16;
    const int swzB = (lane & 7) << 4;

    uint32_t afrag[2][2][4];     // double-buffered across kh
    uint32_t bfrag[4][4];        // single-buffered (reg budget)

    #pragma unroll 1
    for (int it = 0; it < NIT; ++it) {
        const int s = it % STAGES;
        const uint32_t aBase = smem_base + s * STAGE_BYTES;
        const uint32_t bBase = aBase + A_STAGE;
        const bool more = (it + 2 < NIT);
        const int s2 = (it + 2) % STAGES;

        // preload A kh=0 (data for stage s is ready: waited at end of prev iter)
        #pragma unroll
        for (int mi = 0; mi < 2; ++mi) {
            int row = warp_m * 32 + mi * 16 + rA;
            ldsm4(afrag[0][mi], aBase + row * ROWB + (cA ^ swzA));
        }

        #pragma unroll
        for (int kh = 0; kh < 4; ++kh) {
            const int cur = kh & 1, nxt = cur ^ 1;
            #pragma unroll
            for (int np = 0; np < 4; ++np) {
                int row = warp_n * 64 + np * 16 + rB;
                ldsm4(bfrag[np], bBase + row * ROWB + ((kh * 32 + cB) ^ swzB));
            }
            if (kh < 3) {
                #pragma unroll
                for (int mi = 0; mi < 2; ++mi) {
                    int row = warp_m * 32 + mi * 16 + rA;
                    ldsm4(afrag[nxt][mi], aBase + row * ROWB + (((kh + 1) * 32 + cA) ^ swzA));
                }
            }
            // interleave next-next stage global loads into MMA-rich region
            if (kh == 0 && more) issue_A(s2, it + 2);
            if (kh == 1) { if (more) issue_B(s2, it + 2); CP_COMMIT(); }

            #pragma unroll
            for (int np = 0; np < 4; ++np)
                #pragma unroll
                for (int mi = 0; mi < 2; ++mi) {
                    mma16816(acc[mi][2 * np],     afrag[cur][mi], bfrag[np][0], bfrag[np][2]);
                    mma16816(acc[mi][2 * np + 1], afrag[cur][mi], bfrag[np][1], bfrag[np][3]);
                }
        }

        // wait for stage it+1 (committed last iter) before next iter reads it
        CP_WAIT(1);
        __syncthreads();
    }

    // ---- epilogue: streaming float2 stores ----
    const int mBase = m0 + warp_m * 32;
    const int nBase = n0 + warp_n * 64;
    const int r0 = lane >> 2;
    const int cpair = (lane & 3) * 2;
    #pragma unroll
    for (int mi = 0; mi < 2; ++mi) {
        #pragma unroll
        for (int ni = 0; ni < 8; ++ni) {
            float* p0 = out + (size_t)(mBase + mi * 16 + r0) * NDIM + nBase + ni * 8 + cpair;
            float* p1 = out + (size_t)(mBase + mi * 16 + r0 + 8) * NDIM + nBase + ni * 8 + cpair;
            __stcs(reinterpret_cast<float2*>(p0), make_float2(acc[mi][ni][0], acc[mi][ni][1]));
            __stcs(reinterpret_cast<float2*>(p1), make_float2(acc[mi][ni][2], acc[mi][ni][3]));
        }
    }
}

extern "C" void kernel_launch(void* const* d_in, const int* in_sizes, int n_in,
                              void* d_out, int out_size) {
    const float* x  = (const float*)d_in[0];
    const int* qw   = (const int*)d_in[1];
    const int* qz   = (const int*)d_in[2];
    const float* sc = (const float*)d_in[3];
    float* out      = (float*)d_out;

    cudaFuncSetAttribute(gemm_kernel, cudaFuncAttributeMaxDynamicSharedMemorySize, SMEM_TOTAL);

    prep_kernel<<<PREP_BLOCKS, 256>>>(x, qw, qz, sc);
    gemm_kernel<<<GRID_M * GRID_N, THREADS, SMEM_TOTAL>>>(out);
}

// round 10
// speedup vs baseline: 1.4253x; 1.0045x over previous
#include <cuda_runtime.h>
#include <cuda_fp16.h>
#include <cstdint>

// Shapes: x[4,1024,4096] f32, qweight[512,11008] i32 (8x4b along K),
// qzeros[32,1376] i32 (8x4b along N), scales[32,11008] f32, out[4096,11008] f32.
#define MDIM 4096
#define KDIM 4096
#define NDIM 11008

#define BM 128
#define BN 128
#define BK 64
#define STAGES 3
#define THREADS 256
#define NIT (KDIM / BK)          // 64
#define GRID_M (MDIM / BM)       // 32
#define GRID_N (NDIM / BN)       // 86

#define ROWB 128                                  // 128B rows, XOR swizzle
#define A_STAGE (BM * ROWB)                       // 16384
#define B_STAGE (BN * ROWB)                       // 16384
#define STAGE_BYTES (A_STAGE + B_STAGE)           // 32768
#define SMEM_TOTAL (STAGE_BYTES * STAGES)         // 98304  -> 2 CTAs/SM

#define CVT_BLOCKS (MDIM * KDIM / 8 / 256)        // 8192
#define DQ_BX (NDIM / 64)                         // 172
#define DQ_BY (KDIM / 64)                         // 64
#define PREP_BLOCKS (CVT_BLOCKS + DQ_BX * DQ_BY)  // 19200

// fp16 staging of A (x) and dequantized W^T (N-major, K contiguous)
__device__ __align__(16) __half g_xh[(size_t)MDIM * KDIM];   // 33.5 MB
__device__ __align__(16) __half g_wt[(size_t)NDIM * KDIM];   // 90.2 MB

// ---------------- merged prepass: x->fp16  +  dequant/transpose ----------------
__global__ void __launch_bounds__(256) prep_kernel(const float* __restrict__ x,
                                                   const int* __restrict__ qweight,
                                                   const int* __restrict__ qzeros,
                                                   const float* __restrict__ scales) {
    const int t = threadIdx.x;
    if (blockIdx.x < CVT_BLOCKS) {
        size_t idx = (size_t)blockIdx.x * 256 + t;
        const float4* xp = reinterpret_cast<const float4*>(x) + idx * 2;
        float4 a = xp[0], b = xp[1];
        __half2 h0 = __floats2half2_rn(a.x, a.y);
        __half2 h1 = __floats2half2_rn(a.z, a.w);
        __half2 h2 = __floats2half2_rn(b.x, b.y);
        __half2 h3 = __floats2half2_rn(b.z, b.w);
        uint4 o;
        o.x = *reinterpret_cast<uint32_t*>(&h0);
        o.y = *reinterpret_cast<uint32_t*>(&h1);
        o.z = *reinterpret_cast<uint32_t*>(&h2);
        o.w = *reinterpret_cast<uint32_t*>(&h3);
        reinterpret_cast<uint4*>(g_xh)[idx] = o;
        return;
    }
    __shared__ __align__(16) uint8_t tile[64 * 128];
    const int b = blockIdx.x - CVT_BLOCKS;
    const int n0 = (b % DQ_BX) * 64;
    const int by = b / DQ_BX;
    const int k0 = by * 64;
    const int kp0 = by * 8;
    const int g = k0 >> 7;

    const int nl = t & 63;
    const int n = n0 + nl;
    const int z = ((uint32_t)qzeros[g * (NDIM / 8) + (n >> 3)] >> ((n & 7) * 4)) & 0xF;
    const float s = scales[(size_t)g * NDIM + n];

    #pragma unroll
    for (int i = 0; i < 2; ++i) {
        int item = i * 256 + t;
        int kp = item >> 6;
        uint32_t q = (uint32_t)qweight[(size_t)(kp0 + kp) * NDIM + n];
        __half h[8];
        #pragma unroll
        for (int j = 0; j < 8; ++j) {
            int v = (q >> (4 * j)) & 0xF;
            h[j] = __float2half_rn((float)(v - z) * s);
        }
        int colb = (kp * 16) ^ ((nl & 7) << 4);
        *reinterpret_cast<uint4*>(tile + nl * 128 + colb) = *reinterpret_cast<uint4*>(h);
    }
    __syncthreads();
    #pragma unroll
    for (int i = 0; i < 8; ++i) {
        int idx = i * 256 + t;
        int row = idx >> 5, col = idx & 31;
        uint32_t v = *reinterpret_cast<uint32_t*>(tile + row * 128 + ((col * 4) ^ ((row & 7) << 4)));
        __stcs(reinterpret_cast<uint32_t*>(&g_wt[(size_t)(n0 + row) * KDIM + k0 + col * 2]), v);
    }
}

// ---------------- PTX helpers ----------------
__device__ __forceinline__ void ldsm4(uint32_t* r, uint32_t addr) {
    asm volatile("ldmatrix.sync.aligned.m8n8.x4.shared.b16 {%0,%1,%2,%3}, [%4];"
                 : "=r"(r[0]), "=r"(r[1]), "=r"(r[2]), "=r"(r[3]) : "r"(addr));
}
__device__ __forceinline__ void mma16816(float* c, const uint32_t* a, uint32_t b0, uint32_t b1) {
    asm volatile("mma.sync.aligned.m16n8k16.row.col.f32.f16.f16.f32 "
                 "{%0,%1,%2,%3}, {%4,%5,%6,%7}, {%8,%9}, {%0,%1,%2,%3};"
                 : "+f"(c[0]), "+f"(c[1]), "+f"(c[2]), "+f"(c[3])
                 : "r"(a[0]), "r"(a[1]), "r"(a[2]), "r"(a[3]), "r"(b0), "r"(b1));
}
__device__ __forceinline__ void cp_async16(uint32_t dst, const void* src) {
    asm volatile("cp.async.cg.shared.global [%0], [%1], 16;" :: "r"(dst), "l"(src));
}
#define CP_COMMIT() asm volatile("cp.async.commit_group;" ::: "memory")
#define CP_WAIT(N)  asm volatile("cp.async.wait_group %0;" :: "n"(N) : "memory")

// ---------------- main GEMM: 128x128 tile, 2 CTAs/SM, fine-grained pipelining ----------------
__global__ void __launch_bounds__(THREADS, 2) gemm_kernel(float* __restrict__ out) {
    extern __shared__ __align__(16) char smem[];
    const uint32_t smem_base = (uint32_t)__cvta_generic_to_shared(smem);

    const int t = threadIdx.x;
    const int wid = t >> 5;
    const int lane = t & 31;

    const int mtile = blockIdx.x & 31;          // mtile fastest: wave shares A fully + B slices in L2
    const int ntile = blockIdx.x >> 5;
    const int m0 = mtile * BM;
    const int n0 = ntile * BN;

    const int warp_m = wid & 3;                 // 4 slabs x 32 rows
    const int warp_n = wid >> 2;                // 2 slabs x 64 cols

    float acc[2][8][4];
    #pragma unroll
    for (int i = 0; i < 2; ++i)
        #pragma unroll
        for (int j = 0; j < 8; ++j)
            #pragma unroll
            for (int k = 0; k < 4; ++k) acc[i][j][k] = 0.f;

    // per-thread cp.async source/dest components
    const int ldRow = t >> 3;                   // 0..31 (row block step 32)
    const int ldCol = t & 7;                    // 16B chunk
    const uint32_t ldDstOff = ldRow * ROWB + ((ldCol * 16) ^ ((ldRow & 7) << 4));

    // rolling global source pointers (advance by BK per iter; issue targets it+2)
    const __half* srcA = g_xh + (size_t)(m0 + ldRow) * KDIM + ldCol * 8;
    const __half* srcB = g_wt + (size_t)(n0 + ldRow) * KDIM + ldCol * 8;

    auto issue_A = [&](uint32_t dstBase, const __half* src) {
        #pragma unroll
        for (int j = 0; j < 4; ++j)
            cp_async16(dstBase + j * 32 * ROWB, src + (size_t)(j * 32) * KDIM);
    };
    auto issue_B = [&](uint32_t dstBase, const __half* src) {
        #pragma unroll
        for (int j = 0; j < 4; ++j)
            cp_async16(dstBase + A_STAGE + j * 32 * ROWB, src + (size_t)(j * 32) * KDIM);
    };

    // prologue: stages 0 and 1 in flight
    issue_A(smem_base + ldDstOff, srcA);
    issue_B(smem_base + ldDstOff, srcB);
    CP_COMMIT();
    issue_A(smem_base + STAGE_BYTES + ldDstOff, srcA + BK);
    issue_B(smem_base + STAGE_BYTES + ldDstOff, srcB + BK);
    CP_COMMIT();
    srcA += 2 * BK;                              // now points at it+2 source
    srcB += 2 * BK;
    CP_WAIT(1);
    __syncthreads();

    const int rA = lane & 15;
    const int cA = (lane >> 4) * 16;
    const int swzA = (lane & 7) << 4;
    const int rB = ((lane >> 3) & 1) * 8 + (lane & 7);
    const int cB = (lane >> 4) * 16;
    const int swzB = (lane & 7) << 4;

    // warp-level smem row bases (stage-invariant parts)
    const uint32_t aRow0 = (warp_m * 32 + rA) * ROWB;
    const uint32_t bRow0 = (warp_n * 64 + rB) * ROWB;

    uint32_t afrag[2][2][4];     // double-buffered across kh
    uint32_t bfrag[2][2][4];     // slot0: np={0,1}, slot1: np={2,3}

    uint32_t consBase = smem_base;               // stage being consumed
    uint32_t prodBase = smem_base + 2 * STAGE_BYTES;   // stage being filled (it+2)

    #pragma unroll 1
    for (int it = 0; it < NIT; ++it) {
        const uint32_t aBase = consBase;
        const uint32_t bBase = consBase + A_STAGE;
        const bool more = (it + 2 < NIT);

        // preload kh=0: A frags + B slot0 (np 0,1)
        #pragma unroll
        for (int mi = 0; mi < 2; ++mi)
            ldsm4(afrag[0][mi], aBase + aRow0 + mi * 16 * ROWB + (cA ^ swzA));
        #pragma unroll
        for (int np = 0; np < 2; ++np)
            ldsm4(bfrag[0][np], bBase + bRow0 + np * 16 * ROWB + (cB ^ swzB));

        #pragma unroll
        for (int kh = 0; kh < 4; ++kh) {
            const int cur = kh & 1, nxt = cur ^ 1;
            const uint32_t kcol = kh * 32;

            // B slot1 (np 2,3) for this kh
            #pragma unroll
            for (int np = 0; np < 2; ++np)
                ldsm4(bfrag[1][np], bBase + bRow0 + (np + 2) * 16 * ROWB + ((kcol + cB) ^ swzB));
            // A frags for kh+1
            if (kh < 3) {
                #pragma unroll
                for (int mi = 0; mi < 2; ++mi)
                    ldsm4(afrag[nxt][mi], aBase + aRow0 + mi * 16 * ROWB + ((kcol + 32 + cA) ^ swzA));
            }
            // interleave next-next stage global loads into MMA-rich region
            if (kh == 0 && more) issue_A(prodBase + ldDstOff, srcA);
            if (kh == 1) { if (more) issue_B(prodBase + ldDstOff, srcB); CP_COMMIT(); }

            // MMA pair 0 (np 0,1)
            #pragma unroll
            for (int np = 0; np < 2; ++np)
                #pragma unroll
                for (int mi = 0; mi < 2; ++mi) {
                    mma16816(acc[mi][2 * np],     afrag[cur][mi], bfrag[0][np][0], bfrag[0][np][2]);
                    mma16816(acc[mi][2 * np + 1], afrag[cur][mi], bfrag[0][np][1], bfrag[0][np][3]);
                }
            // B slot0 (np 0,1) for kh+1, hidden under pair-1 MMAs
            if (kh < 3) {
                #pragma unroll
                for (int np = 0; np < 2; ++np)
                    ldsm4(bfrag[0][np], bBase + bRow0 + np * 16 * ROWB + ((kcol + 32 + cB) ^ swzB));
            }
            // MMA pair 1 (np 2,3)
            #pragma unroll
            for (int np = 0; np < 2; ++np)
                #pragma unroll
                for (int mi = 0; mi < 2; ++mi) {
                    mma16816(acc[mi][4 + 2 * np],     afrag[cur][mi], bfrag[1][np][0], bfrag[1][np][2]);
                    mma16816(acc[mi][4 + 2 * np + 1], afrag[cur][mi], bfrag[1][np][1], bfrag[1][np][3]);
                }
        }

        // rotate stages, advance sources
        consBase += STAGE_BYTES;
        if (consBase == smem_base + 3 * STAGE_BYTES) consBase = smem_base;
        prodBase += STAGE_BYTES;
        if (prodBase == smem_base + 3 * STAGE_BYTES) prodBase = smem_base;
        srcA += BK;
        srcB += BK;

        // wait for stage it+1 (committed last iter) before next iter reads it
        CP_WAIT(1);
        __syncthreads();
    }

    // ---- epilogue: streaming float2 stores ----
    const int mBase = m0 + warp_m * 32;
    const int nBase = n0 + warp_n * 64;
    const int r0 = lane >> 2;
    const int cpair = (lane & 3) * 2;
    #pragma unroll
    for (int mi = 0; mi < 2; ++mi) {
        #pragma unroll
        for (int ni = 0; ni < 8; ++ni) {
            float* p0 = out + (size_t)(mBase + mi * 16 + r0) * NDIM + nBase + ni * 8 + cpair;
            float* p1 = out + (size_t)(mBase + mi * 16 + r0 + 8) * NDIM + nBase + ni * 8 + cpair;
            __stcs(reinterpret_cast<float2*>(p0), make_float2(acc[mi][ni][0], acc[mi][ni][1]));
            __stcs(reinterpret_cast<float2*>(p1), make_float2(acc[mi][ni][2], acc[mi][ni][3]));
        }
    }
}

extern "C" void kernel_launch(void* const* d_in, const int* in_sizes, int n_in,
                              void* d_out, int out_size) {
    const float* x  = (const float*)d_in[0];
    const int* qw   = (const int*)d_in[1];
    const int* qz   = (const int*)d_in[2];
    const float* sc = (const float*)d_in[3];
    float* out      = (float*)d_out;

    cudaFuncSetAttribute(gemm_kernel, cudaFuncAttributeMaxDynamicSharedMemorySize, SMEM_TOTAL);

    prep_kernel<<<PREP_BLOCKS, 256>>>(x, qw, qz, sc);
    gemm_kernel<<<GRID_M * GRID_N, THREADS, SMEM_TOTAL>>>(out);
}